// round 1
// baseline (speedup 1.0000x reference)
#include <cuda_runtime.h>
#include <cuda_bf16.h>
#include <math.h>

// Problem constants
#define NTOK   65536        // 32*2048 tokens
#define DIM    64
#define KCODES 1024
#define CHUNK  64           // codes per shared-memory tile

// Output layout (concatenation of reference tuple, float32)
#define OFF_Q    0                        // st_quantized [32,2048,64] = 4194304
#define OFF_CM   4194304                  // commitment_loss
#define OFF_CB   4194305                  // codebook_loss
#define OFF_P    4194306                  // perplexity
#define OFF_E    4194307                  // new_embedding [1024,64]
#define OFF_CNT  (OFF_E + KCODES*DIM)     // new_count [1024]
#define OFF_W    (OFF_CNT + KCODES)       // new_weight [1024,64]
#define OFF_USE  (OFF_W + KCODES*DIM)     // new_usage [1024]

// Scratch (no cudaMalloc allowed)
__device__ float  g_counts[KCODES];
__device__ float  g_dw[KCODES * DIM];
__device__ float  g_enorm[KCODES];
__device__ double g_loss;

// ---------------------------------------------------------------------------
// Kernel 0: zero scratch + precompute ||e||^2  (runs every graph replay)
// ---------------------------------------------------------------------------
__global__ void setup_kernel(const float* __restrict__ emb) {
    int b = blockIdx.x;
    int t = threadIdx.x;
    if (b < 64) {
        g_dw[b * 1024 + t] = 0.0f;
    } else {
        g_counts[t] = 0.0f;
        if (t == 0) g_loss = 0.0;
        // enorm[t] = sum_d e[t][d]^2 (sequential fp32 fma, ascending d)
        const float* er = emb + (size_t)t * DIM;
        float s = 0.0f;
        #pragma unroll 8
        for (int d = 0; d < DIM; d++) s = __fmaf_rn(er[d], er[d], s);
        g_enorm[t] = s;
    }
}

// ---------------------------------------------------------------------------
// Kernel 1: per-token argmin over K codes (f32x2 packed FMA), quantized write,
//           loss partial, counts + dw atomics.
// ---------------------------------------------------------------------------
__global__ __launch_bounds__(128)
void assign_kernel(const float* __restrict__ x,
                   const float* __restrict__ emb,
                   float* __restrict__ out) {
    __shared__ __align__(16) float se[CHUNK * DIM];
    __shared__ float sen[CHUNK];

    int token = blockIdx.x * 128 + threadIdx.x;
    if (token >= NTOK) return;   // grid is exact; guard is free

    // ---- load x row, packed as 32 f32x2 pairs; compute xnorm ----
    unsigned long long xr[32];
    float xn = 0.0f;
    {
        const float4* xrow = reinterpret_cast<const float4*>(x + (size_t)token * DIM);
        #pragma unroll
        for (int j = 0; j < 16; j++) {
            float4 v = __ldg(&xrow[j]);
            asm("mov.b64 %0, {%1, %2};" : "=l"(xr[2*j])   : "f"(v.x), "f"(v.y));
            asm("mov.b64 %0, {%1, %2};" : "=l"(xr[2*j+1]) : "f"(v.z), "f"(v.w));
            xn = __fmaf_rn(v.x, v.x, xn);
            xn = __fmaf_rn(v.y, v.y, xn);
            xn = __fmaf_rn(v.z, v.z, xn);
            xn = __fmaf_rn(v.w, v.w, xn);
        }
    }

    float best = 3.402823466e+38f;
    int   bi   = 0;

    for (int c0 = 0; c0 < KCODES; c0 += CHUNK) {
        __syncthreads();
        // cooperative tile load: CHUNK*DIM floats = 1024 float4, 128 threads
        {
            const float4* esrc = reinterpret_cast<const float4*>(emb + (size_t)c0 * DIM);
            float4* edst = reinterpret_cast<float4*>(se);
            #pragma unroll
            for (int j = 0; j < (CHUNK * DIM / 4) / 128; j++)
                edst[j * 128 + threadIdx.x] = __ldg(&esrc[j * 128 + threadIdx.x]);
            if (threadIdx.x < CHUNK) sen[threadIdx.x] = g_enorm[c0 + threadIdx.x];
        }
        __syncthreads();

        for (int k = 0; k < CHUNK; k++) {
            const ulonglong2* ep = reinterpret_cast<const ulonglong2*>(&se[k * DIM]);
            unsigned long long a0 = 0ull, a1 = 0ull, a2 = 0ull, a3 = 0ull;
            #pragma unroll
            for (int j = 0; j < 16; j += 2) {
                ulonglong2 e0 = ep[j];
                ulonglong2 e1 = ep[j + 1];
                asm("fma.rn.f32x2 %0, %1, %2, %0;" : "+l"(a0) : "l"(xr[2*j]),   "l"(e0.x));
                asm("fma.rn.f32x2 %0, %1, %2, %0;" : "+l"(a1) : "l"(xr[2*j+1]), "l"(e0.y));
                asm("fma.rn.f32x2 %0, %1, %2, %0;" : "+l"(a2) : "l"(xr[2*j+2]), "l"(e1.x));
                asm("fma.rn.f32x2 %0, %1, %2, %0;" : "+l"(a3) : "l"(xr[2*j+3]), "l"(e1.y));
            }
            float l0, h0, l1, h1, l2, h2, l3, h3;
            asm("mov.b64 {%0, %1}, %2;" : "=f"(l0), "=f"(h0) : "l"(a0));
            asm("mov.b64 {%0, %1}, %2;" : "=f"(l1), "=f"(h1) : "l"(a1));
            asm("mov.b64 {%0, %1}, %2;" : "=f"(l2), "=f"(h2) : "l"(a2));
            asm("mov.b64 {%0, %1}, %2;" : "=f"(l3), "=f"(h3) : "l"(a3));
            float dot = __fadd_rn(__fadd_rn(__fadd_rn(l0, h0), __fadd_rn(l1, h1)),
                                  __fadd_rn(__fadd_rn(l2, h2), __fadd_rn(l3, h3)));
            // replicate reference rounding: fl(fl(xn - 2*dot) + en)
            float d2 = __fadd_rn(__fadd_rn(xn, -2.0f * dot), sen[k]);
            if (d2 < best) { best = d2; bi = c0 + k; }
        }
    }

    // ---- epilogue: gather e[bi], write st_quantized, loss, counts, dw ----
    float lsum = 0.0f;
    {
        const float4* erow = reinterpret_cast<const float4*>(emb + (size_t)bi * DIM);
        float4* orow = reinterpret_cast<float4*>(out + OFF_Q + (size_t)token * DIM);
        float* dwrow = g_dw + (size_t)bi * DIM;
        #pragma unroll
        for (int j = 0; j < 16; j++) {
            float4 q = __ldg(&erow[j]);
            float x0, x1, x2, x3;
            asm("mov.b64 {%0, %1}, %2;" : "=f"(x0), "=f"(x1) : "l"(xr[2*j]));
            asm("mov.b64 {%0, %1}, %2;" : "=f"(x2), "=f"(x3) : "l"(xr[2*j+1]));
            // st_quantized = x + fl(q - x), replicating reference rounding
            float4 o;
            o.x = __fadd_rn(x0, __fadd_rn(q.x, -x0));
            o.y = __fadd_rn(x1, __fadd_rn(q.y, -x1));
            o.z = __fadd_rn(x2, __fadd_rn(q.z, -x2));
            o.w = __fadd_rn(x3, __fadd_rn(q.w, -x3));
            orow[j] = o;
            float d0 = __fadd_rn(x0, -q.x);
            float d1 = __fadd_rn(x1, -q.y);
            float d2_ = __fadd_rn(x2, -q.z);
            float d3 = __fadd_rn(x3, -q.w);
            lsum = __fmaf_rn(d0, d0, lsum);
            lsum = __fmaf_rn(d1, d1, lsum);
            lsum = __fmaf_rn(d2_, d2_, lsum);
            lsum = __fmaf_rn(d3, d3, lsum);
            atomicAdd(&dwrow[4*j + 0], x0);
            atomicAdd(&dwrow[4*j + 1], x1);
            atomicAdd(&dwrow[4*j + 2], x2);
            atomicAdd(&dwrow[4*j + 3], x3);
        }
    }
    atomicAdd(&g_counts[bi], 1.0f);

    // loss: warp-reduce in double, lane0 atomics
    double dl = (double)lsum;
    #pragma unroll
    for (int off = 16; off > 0; off >>= 1)
        dl += __shfl_down_sync(0xffffffffu, dl, off);
    if ((threadIdx.x & 31) == 0) atomicAdd(&g_loss, dl);
}

// ---------------------------------------------------------------------------
// Kernel 2: K-sized reductions + EMA updates + scalars (one block, 1024 thr)
// ---------------------------------------------------------------------------
__global__ void finalize_kernel(const float* __restrict__ ema_count,
                                const float* __restrict__ ema_weight,
                                const float* __restrict__ usage,
                                float* __restrict__ out) {
    __shared__ float red_n[1024];
    __shared__ float red_s[1024];
    int k = threadIdx.x;

    float c   = g_counts[k];
    // raw = DECAY*ema_count + (1-DECAY)*counts, reference rounding
    float raw = __fadd_rn(__fmul_rn(0.999f, ema_count[k]), __fmul_rn(0.001f, c));

    float p    = c * (1.0f / 65536.0f);                 // exact (power of two)
    float ent  = __fmul_rn(p, logf(__fadd_rn(p, 1e-10f)));

    red_n[k] = raw;
    red_s[k] = ent;
    __syncthreads();
    for (int s = 512; s > 0; s >>= 1) {
        if (k < s) {
            red_n[k] = __fadd_rn(red_n[k], red_n[k + s]);
            red_s[k] = __fadd_rn(red_s[k], red_s[k + s]);
        }
        __syncthreads();
    }
    float n = red_n[0];
    float ssum = red_s[0];

    // laplace smoothing: ((raw + EPS) / (n + K*EPS)) * n
    float ncnt = __fmul_rn(__fdiv_rn(__fadd_rn(raw, 1e-5f),
                                     __fadd_rn(n, 0.01024f)), n);

    out[OFF_CNT + k] = ncnt;
    out[OFF_USE + k] = __fmul_rn(__fadd_rn(usage[k], (c > 0.0f) ? 1.0f : 0.0f), 0.5f);

    const float* ewr = ema_weight + (size_t)k * DIM;
    const float* dwr = g_dw + (size_t)k * DIM;
    float* ow = out + OFF_W + (size_t)k * DIM;
    float* oe = out + OFF_E + (size_t)k * DIM;
    #pragma unroll 4
    for (int d = 0; d < DIM; d++) {
        float nw = __fadd_rn(__fmul_rn(0.999f, ewr[d]), __fmul_rn(0.001f, dwr[d]));
        ow[d] = nw;
        oe[d] = __fdiv_rn(nw, ncnt);
    }

    if (k == 0) {
        float ml = (float)(g_loss * (1.0 / 4194304.0));  // mean over N*D
        out[OFF_CB] = ml;
        out[OFF_CM] = 0.25f * ml;
        out[OFF_P]  = expf(-ssum);
    }
}

// ---------------------------------------------------------------------------
extern "C" void kernel_launch(void* const* d_in, const int* in_sizes, int n_in,
                              void* d_out, int out_size) {
    const float* x          = (const float*)d_in[0];
    const float* emb        = (const float*)d_in[1];
    const float* ema_count  = (const float*)d_in[2];
    const float* ema_weight = (const float*)d_in[3];
    const float* usage      = (const float*)d_in[4];
    float* out = (float*)d_out;

    setup_kernel<<<65, 1024>>>(emb);
    assign_kernel<<<NTOK / 128, 128>>>(x, emb, out);
    finalize_kernel<<<1, 1024>>>(ema_count, ema_weight, usage, out);
}

// round 2
// speedup vs baseline: 1.6838x; 1.6838x over previous
#include <cuda_runtime.h>
#include <cuda_bf16.h>
#include <math.h>
#include <float.h>

// Problem constants
#define NTOK   65536        // 32*2048 tokens
#define DIM    64
#define KCODES 1024
#define CHUNK  128          // codes per shared tile
#define NCHUNK (KCODES / CHUNK)          // 8
#define NTTILE (NTOK / 256)              // 256 token tiles of 256 tokens
#define NTILES (NCHUNK * NTTILE)         // 2048 work units
#define GRID_ASSIGN 296                  // 2 CTAs per SM * 148 SMs

// Output layout (concatenation of reference tuple, float32)
#define OFF_Q    0
#define OFF_CM   4194304
#define OFF_CB   4194305
#define OFF_P    4194306
#define OFF_E    4194307
#define OFF_CNT  (OFF_E + KCODES*DIM)
#define OFF_W    (OFF_CNT + KCODES)
#define OFF_USE  (OFF_W + KCODES*DIM)

// Scratch (no cudaMalloc allowed)
__device__ float              g_counts[KCODES];
__device__ float              g_dw[KCODES * DIM];
__device__ float              g_enorm[KCODES];
__device__ unsigned long long g_best[NTOK];
__device__ double             g_loss;

// ---- f32x2 helpers -------------------------------------------------------
__device__ __forceinline__ void fma2(unsigned long long& a,
                                     unsigned long long x, unsigned long long e) {
    asm("fma.rn.f32x2 %0, %1, %2, %0;" : "+l"(a) : "l"(x), "l"(e));
}
__device__ __forceinline__ unsigned long long mul2(unsigned long long x,
                                                   unsigned long long e) {
    unsigned long long r;
    asm("mul.rn.f32x2 %0, %1, %2;" : "=l"(r) : "l"(x), "l"(e));
    return r;
}
__device__ __forceinline__ unsigned long long add2(unsigned long long a,
                                                   unsigned long long b) {
    unsigned long long r;
    asm("add.rn.f32x2 %0, %1, %2;" : "=l"(r) : "l"(a), "l"(b));
    return r;
}
__device__ __forceinline__ unsigned long long pack2(float lo, float hi) {
    unsigned long long r;
    asm("mov.b64 %0, {%1, %2};" : "=l"(r) : "f"(lo), "f"(hi));
    return r;
}

// ---------------------------------------------------------------------------
// Kernel 0: zero scratch, init g_best, compute ||e||^2 (coalesced, parallel)
// ---------------------------------------------------------------------------
__global__ void setup_kernel(const float* __restrict__ emb) {
    int gtid = blockIdx.x * 256 + threadIdx.x;      // 0..65535
    g_best[gtid] = 0xFFFFFFFFFFFFFFFFull;
    g_dw[gtid]   = 0.0f;
    if (gtid < KCODES) g_counts[gtid] = 0.0f;
    if (gtid == 0)     g_loss = 0.0;

    if (blockIdx.x < 64) {
        int code = blockIdx.x * 16 + (threadIdx.x >> 4);
        int sub  = threadIdx.x & 15;
        float4 v = __ldg(((const float4*)(emb + (size_t)code * DIM)) + sub);
        float s = __fmul_rn(v.x, v.x);
        s = __fmaf_rn(v.y, v.y, s);
        s = __fmaf_rn(v.z, v.z, s);
        s = __fmaf_rn(v.w, v.w, s);
        #pragma unroll
        for (int off = 8; off > 0; off >>= 1)
            s = __fadd_rn(s, __shfl_down_sync(0xffffffffu, s, off));
        if (sub == 0) g_enorm[code] = s;
    }
}

// ---------------------------------------------------------------------------
// Kernel 1: argmin pass. Work unit = (256-token tile) x (128-code chunk).
//           2048 units over 296 CTAs -> 98.8% balance. Result via u64
//           atomicMin key = (d2_bits << 32) | code_idx (exact jnp tie-break).
// ---------------------------------------------------------------------------
__global__ __launch_bounds__(256, 2)
void assign_kernel(const float* __restrict__ x,
                   const float* __restrict__ emb) {
    __shared__ __align__(16) float se[CHUNK * DIM];   // 32 KB
    __shared__ float sen[CHUNK];

    for (int t = blockIdx.x; t < NTILES; t += GRID_ASSIGN) {
        int chunk  = t >> 8;              // 0..7
        int ttile  = t & 255;             // 0..255
        int token  = (ttile << 8) + threadIdx.x;
        int c_base = chunk << 7;

        // ---- load x row as 32 f32x2 pairs, compute xnorm ----
        unsigned long long xr[32];
        float xn = 0.0f;
        {
            const float4* xrow = (const float4*)(x + ((size_t)token << 6));
            #pragma unroll
            for (int j = 0; j < 16; j++) {
                float4 v = __ldg(xrow + j);
                xr[2*j]   = pack2(v.x, v.y);
                xr[2*j+1] = pack2(v.z, v.w);
                xn = __fmaf_rn(v.x, v.x, xn);
                xn = __fmaf_rn(v.y, v.y, xn);
                xn = __fmaf_rn(v.z, v.z, xn);
                xn = __fmaf_rn(v.w, v.w, xn);
            }
        }

        __syncthreads();   // protect smem from previous tile's readers
        {
            const float4* esrc = (const float4*)(emb + ((size_t)c_base << 6));
            float4* edst = (float4*)se;
            #pragma unroll
            for (int j = 0; j < 8; j++)
                edst[j * 256 + threadIdx.x] = __ldg(esrc + j * 256 + threadIdx.x);
            if (threadIdx.x < CHUNK) sen[threadIdx.x] = g_enorm[c_base + threadIdx.x];
        }
        __syncthreads();

        float best = FLT_MAX;
        int   bi   = 0;

        #pragma unroll 4
        for (int k = 0; k < CHUNK; k++) {
            const ulonglong2* ep = (const ulonglong2*)(se + (k << 6));
            ulonglong2 qa = ep[0], qb = ep[1];
            unsigned long long a0 = mul2(xr[0], qa.x);
            unsigned long long a1 = mul2(xr[1], qa.y);
            unsigned long long a2 = mul2(xr[2], qb.x);
            unsigned long long a3 = mul2(xr[3], qb.y);
            #pragma unroll
            for (int j = 1; j < 8; j++) {
                qa = ep[2*j];
                qb = ep[2*j + 1];
                fma2(a0, xr[4*j + 0], qa.x);
                fma2(a1, xr[4*j + 1], qa.y);
                fma2(a2, xr[4*j + 2], qb.x);
                fma2(a3, xr[4*j + 3], qb.y);
            }
            a0 = add2(a0, a1);
            a2 = add2(a2, a3);
            a0 = add2(a0, a2);
            float lo, hi;
            asm("mov.b64 {%0, %1}, %2;" : "=f"(lo), "=f"(hi) : "l"(a0));
            float dot = __fadd_rn(lo, hi);
            // fma(-2,dot,xn) == fl(xn - 2*dot) exactly (2*dot exact product)
            float d2 = __fadd_rn(__fmaf_rn(-2.0f, dot, xn), sen[k]);
            if (d2 < best) { best = d2; bi = c_base + k; }
        }

        unsigned long long key =
            ((unsigned long long)__float_as_uint(best) << 32) | (unsigned)bi;
        atomicMin(&g_best[token], key);
    }
}

// ---------------------------------------------------------------------------
// Kernel 2: per-token epilogue — quantized write, loss, counts, dw atomics
// ---------------------------------------------------------------------------
__global__ __launch_bounds__(256)
void epilogue_kernel(const float* __restrict__ x,
                     const float* __restrict__ emb,
                     float* __restrict__ out) {
    int token = blockIdx.x * 256 + threadIdx.x;
    int bi = (int)(g_best[token] & 0xFFFFFFFFull);

    const float4* xrow = (const float4*)(x + ((size_t)token << 6));
    const float4* erow = (const float4*)(emb + ((size_t)bi << 6));
    float4* orow = (float4*)(out + OFF_Q + ((size_t)token << 6));
    float* dwrow = g_dw + ((size_t)bi << 6);

    float lsum = 0.0f;
    #pragma unroll 4
    for (int j = 0; j < 16; j++) {
        float4 xv = __ldg(xrow + j);
        float4 q  = __ldg(erow + j);
        float4 o;
        o.x = __fadd_rn(xv.x, __fadd_rn(q.x, -xv.x));
        o.y = __fadd_rn(xv.y, __fadd_rn(q.y, -xv.y));
        o.z = __fadd_rn(xv.z, __fadd_rn(q.z, -xv.z));
        o.w = __fadd_rn(xv.w, __fadd_rn(q.w, -xv.w));
        orow[j] = o;
        float d0 = __fadd_rn(xv.x, -q.x);
        float d1 = __fadd_rn(xv.y, -q.y);
        float d2 = __fadd_rn(xv.z, -q.z);
        float d3 = __fadd_rn(xv.w, -q.w);
        lsum = __fmaf_rn(d0, d0, lsum);
        lsum = __fmaf_rn(d1, d1, lsum);
        lsum = __fmaf_rn(d2, d2, lsum);
        lsum = __fmaf_rn(d3, d3, lsum);
        atomicAdd(dwrow + 4*j + 0, xv.x);
        atomicAdd(dwrow + 4*j + 1, xv.y);
        atomicAdd(dwrow + 4*j + 2, xv.z);
        atomicAdd(dwrow + 4*j + 3, xv.w);
    }
    atomicAdd(&g_counts[bi], 1.0f);

    double dl = (double)lsum;
    #pragma unroll
    for (int off = 16; off > 0; off >>= 1)
        dl += __shfl_down_sync(0xffffffffu, dl, off);
    if ((threadIdx.x & 31) == 0) atomicAdd(&g_loss, dl);
}

// ---------------------------------------------------------------------------
// Kernel 3: K-sized reductions + scalars + counts/usage (one 1024-thread CTA)
// ---------------------------------------------------------------------------
__global__ void finalize_kernel(const float* __restrict__ ema_count,
                                const float* __restrict__ usage,
                                float* __restrict__ out) {
    __shared__ float red_n[1024];
    __shared__ float red_s[1024];
    int k = threadIdx.x;

    float c   = g_counts[k];
    float raw = __fadd_rn(__fmul_rn(0.999f, ema_count[k]), __fmul_rn(0.001f, c));

    float p   = c * (1.0f / 65536.0f);
    float ent = __fmul_rn(p, logf(__fadd_rn(p, 1e-10f)));

    red_n[k] = raw;
    red_s[k] = ent;
    __syncthreads();
    for (int s = 512; s > 0; s >>= 1) {
        if (k < s) {
            red_n[k] = __fadd_rn(red_n[k], red_n[k + s]);
            red_s[k] = __fadd_rn(red_s[k], red_s[k + s]);
        }
        __syncthreads();
    }
    float n    = red_n[0];
    float ssum = red_s[0];

    float ncnt = __fmul_rn(__fdiv_rn(__fadd_rn(raw, 1e-5f),
                                     __fadd_rn(n, 0.01024f)), n);
    out[OFF_CNT + k] = ncnt;
    out[OFF_USE + k] = __fmul_rn(__fadd_rn(usage[k], (c > 0.0f) ? 1.0f : 0.0f), 0.5f);

    if (k == 0) {
        float ml = (float)(g_loss * (1.0 / 4194304.0));
        out[OFF_CB] = ml;
        out[OFF_CM] = 0.25f * ml;
        out[OFF_P]  = expf(-ssum);
    }
}

// ---------------------------------------------------------------------------
// Kernel 4: new_weight / new_embedding (coalesced, reads ncnt from out)
// ---------------------------------------------------------------------------
__global__ void ema_kernel(const float* __restrict__ ema_weight,
                           float* __restrict__ out) {
    int idx = blockIdx.x * 1024 + threadIdx.x;      // 0..65535
    float nw = __fadd_rn(__fmul_rn(0.999f, ema_weight[idx]),
                         __fmul_rn(0.001f, g_dw[idx]));
    out[OFF_W + idx] = nw;
    out[OFF_E + idx] = __fdiv_rn(nw, out[OFF_CNT + (idx >> 6)]);
}

// ---------------------------------------------------------------------------
extern "C" void kernel_launch(void* const* d_in, const int* in_sizes, int n_in,
                              void* d_out, int out_size) {
    const float* x          = (const float*)d_in[0];
    const float* emb        = (const float*)d_in[1];
    const float* ema_count  = (const float*)d_in[2];
    const float* ema_weight = (const float*)d_in[3];
    const float* usage      = (const float*)d_in[4];
    float* out = (float*)d_out;

    setup_kernel<<<256, 256>>>(emb);
    assign_kernel<<<GRID_ASSIGN, 256>>>(x, emb);
    epilogue_kernel<<<NTOK / 256, 256>>>(x, emb, out);
    finalize_kernel<<<1, 1024>>>(ema_count, usage, out);
    ema_kernel<<<64, 1024>>>(ema_weight, out);
}

// round 3
// speedup vs baseline: 1.9644x; 1.1666x over previous
#include <cuda_runtime.h>
#include <math.h>
#include <float.h>

// Problem constants
#define NTOK   65536
#define DIM    64
#define KCODES 1024
#define MARGIN 5e-4f

// Output layout (float32 concatenation of the reference tuple)
#define OFF_Q    0
#define OFF_CM   4194304
#define OFF_CB   4194305
#define OFF_P    4194306
#define OFF_E    4194307
#define OFF_CNT  (OFF_E + KCODES*DIM)
#define OFF_W    (OFF_CNT + KCODES)
#define OFF_USE  (OFF_W + KCODES*DIM)

// Scratch (static device globals; no cudaMalloc allowed)
__device__ float  g_counts[KCODES];
__device__ float  g_dw[KCODES * DIM];
__device__ float  g_enorm[KCODES];
__device__ float  g_ehi[KCODES * DIM];   // tf32 hi parts (bit patterns as float)
__device__ float  g_elo[KCODES * DIM];   // tf32 lo parts
__device__ int    g_idx[NTOK];
__device__ int    g_flag[NTOK];
__device__ int    g_nflag;
__device__ double g_loss;

__device__ __forceinline__ unsigned f2tf32(float f) {
    unsigned r;
    asm("cvt.rna.tf32.f32 %0, %1;" : "=r"(r) : "f"(f));
    return r;
}

#define MMA_TF32(d0,d1,d2,d3,a0,a1,a2,a3,b0,b1)                               \
    asm("mma.sync.aligned.m16n8k8.row.col.f32.tf32.tf32.f32 "                 \
        "{%0,%1,%2,%3}, {%4,%5,%6,%7}, {%8,%9}, {%0,%1,%2,%3};"               \
        : "+f"(d0), "+f"(d1), "+f"(d2), "+f"(d3)                              \
        : "r"(a0), "r"(a1), "r"(a2), "r"(a3), "r"(b0), "r"(b1))

// ---------------------------------------------------------------------------
// Kernel 0: zero scratch; precompute ||e||^2 (same tree as R2) and e hi/lo
// ---------------------------------------------------------------------------
__global__ void setup_kernel(const float* __restrict__ emb) {
    int gtid = blockIdx.x * 256 + threadIdx.x;      // 0..65535
    g_dw[gtid] = 0.0f;
    if (gtid < KCODES) g_counts[gtid] = 0.0f;
    if (gtid == 0) { g_loss = 0.0; g_nflag = 0; }

    // tf32 split of embedding
    float e = __ldg(emb + gtid);
    unsigned hb = f2tf32(e);
    float hf = __uint_as_float(hb);
    g_ehi[gtid] = hf;
    g_elo[gtid] = __uint_as_float(f2tf32(__fadd_rn(e, -hf)));

    // enorm (identical reduction tree to the passing R2 kernel)
    if (blockIdx.x < 64) {
        int code = blockIdx.x * 16 + (threadIdx.x >> 4);
        int sub  = threadIdx.x & 15;
        float4 v = __ldg(((const float4*)(emb + (size_t)code * DIM)) + sub);
        float s = __fmul_rn(v.x, v.x);
        s = __fmaf_rn(v.y, v.y, s);
        s = __fmaf_rn(v.z, v.z, s);
        s = __fmaf_rn(v.w, v.w, s);
        #pragma unroll
        for (int off = 8; off > 0; off >>= 1)
            s = __fadd_rn(s, __shfl_down_sync(0xffffffffu, s, off));
        if (sub == 0) g_enorm[code] = s;
    }
}

// ---------------------------------------------------------------------------
// Kernel 1: 3xTF32 tensor-core approx distance + per-token best1/best2 track.
//           CTA = 128 tokens, warp = 16 tokens over all 1024 codes.
// ---------------------------------------------------------------------------
__global__ __launch_bounds__(256, 2)
void mma_assign_kernel(const float* __restrict__ x) {
    __shared__ __align__(16) float sh_ehi[64 * 68];   // 64 codes, stride 68 (pad)
    __shared__ __align__(16) float sh_elo[64 * 68];
    __shared__ float sh_en[KCODES];

    int tid  = threadIdx.x;
    int lane = tid & 31;
    int wid  = tid >> 5;
    int r    = lane >> 2;    // groupID: row within fragment
    int q    = lane & 3;     // threadID in group
    int warp_tok = blockIdx.x * 128 + wid * 16;

    #pragma unroll
    for (int i = 0; i < 4; i++) sh_en[i * 256 + tid] = g_enorm[i * 256 + tid];

    // ---- A fragments (tf32 hi/lo) + approx xn via quad reduce ----
    unsigned ah[8][4], al[8][4];
    float xn_lo = 0.0f, xn_hi = 0.0f;
    {
        const float* xlo = x + (size_t)(warp_tok + r) * DIM;
        const float* xhi = x + (size_t)(warp_tok + r + 8) * DIM;
        #pragma unroll
        for (int ks = 0; ks < 8; ks++) {
            float v0 = __ldg(xlo + ks * 8 + q);
            float v1 = __ldg(xhi + ks * 8 + q);
            float v2 = __ldg(xlo + ks * 8 + q + 4);
            float v3 = __ldg(xhi + ks * 8 + q + 4);
            xn_lo = __fmaf_rn(v0, v0, xn_lo);
            xn_hi = __fmaf_rn(v1, v1, xn_hi);
            xn_lo = __fmaf_rn(v2, v2, xn_lo);
            xn_hi = __fmaf_rn(v3, v3, xn_hi);
            unsigned h;
            h = f2tf32(v0); ah[ks][0] = h;
            al[ks][0] = f2tf32(__fadd_rn(v0, -__uint_as_float(h)));
            h = f2tf32(v1); ah[ks][1] = h;
            al[ks][1] = f2tf32(__fadd_rn(v1, -__uint_as_float(h)));
            h = f2tf32(v2); ah[ks][2] = h;
            al[ks][2] = f2tf32(__fadd_rn(v2, -__uint_as_float(h)));
            h = f2tf32(v3); ah[ks][3] = h;
            al[ks][3] = f2tf32(__fadd_rn(v3, -__uint_as_float(h)));
        }
        xn_lo += __shfl_xor_sync(0xffffffffu, xn_lo, 1);
        xn_lo += __shfl_xor_sync(0xffffffffu, xn_lo, 2);
        xn_hi += __shfl_xor_sync(0xffffffffu, xn_hi, 1);
        xn_hi += __shfl_xor_sync(0xffffffffu, xn_hi, 2);
    }

    float b1_lo = FLT_MAX, b2_lo = FLT_MAX; int i1_lo = 0;
    float b1_hi = FLT_MAX, b2_hi = FLT_MAX; int i1_hi = 0;

    for (int chunk = 0; chunk < 16; chunk++) {
        __syncthreads();
        // stage 64-code chunk of e hi/lo into padded smem (conflict-free)
        {
            const float4* srch = (const float4*)(g_ehi + chunk * 4096);
            const float4* srcl = (const float4*)(g_elo + chunk * 4096);
            #pragma unroll
            for (int i = 0; i < 4; i++) {
                int idx = i * 256 + tid;          // 0..1023 float4s
                int row = idx >> 4;
                int col = (idx & 15) * 4;
                *(float4*)&sh_ehi[row * 68 + col] = __ldg(srch + idx);
                *(float4*)&sh_elo[row * 68 + col] = __ldg(srcl + idx);
            }
        }
        __syncthreads();

        #pragma unroll 1
        for (int nsub = 0; nsub < 8; nsub++) {
            float hh0 = 0, hh1 = 0, hh2 = 0, hh3 = 0;
            float hl0 = 0, hl1 = 0, hl2 = 0, hl3 = 0;
            float lh0 = 0, lh1 = 0, lh2 = 0, lh3 = 0;
            int brow = (nsub * 8 + r) * 68;
            #pragma unroll
            for (int ks = 0; ks < 8; ks++) {
                unsigned bh0 = __float_as_uint(sh_ehi[brow + ks * 8 + q]);
                unsigned bh1 = __float_as_uint(sh_ehi[brow + ks * 8 + q + 4]);
                unsigned bl0 = __float_as_uint(sh_elo[brow + ks * 8 + q]);
                unsigned bl1 = __float_as_uint(sh_elo[brow + ks * 8 + q + 4]);
                MMA_TF32(hh0, hh1, hh2, hh3,
                         ah[ks][0], ah[ks][1], ah[ks][2], ah[ks][3], bh0, bh1);
                MMA_TF32(hl0, hl1, hl2, hl3,
                         ah[ks][0], ah[ks][1], ah[ks][2], ah[ks][3], bl0, bl1);
                MMA_TF32(lh0, lh1, lh2, lh3,
                         al[ks][0], al[ks][1], al[ks][2], al[ks][3], bh0, bh1);
            }
            float s0 = hh0 + (hl0 + lh0);   // (row r,    col 2q)
            float s1 = hh1 + (hl1 + lh1);   // (row r,    col 2q+1)
            float s2 = hh2 + (hl2 + lh2);   // (row r+8,  col 2q)
            float s3 = hh3 + (hl3 + lh3);   // (row r+8,  col 2q+1)

            int c0 = chunk * 64 + nsub * 8 + q * 2;
            float en0 = sh_en[c0], en1 = sh_en[c0 + 1];
            float d00 = __fmaf_rn(-2.0f, s0, xn_lo) + en0;
            float d01 = __fmaf_rn(-2.0f, s1, xn_lo) + en1;
            float d10 = __fmaf_rn(-2.0f, s2, xn_hi) + en0;
            float d11 = __fmaf_rn(-2.0f, s3, xn_hi) + en1;

            if (d00 < b1_lo) { b2_lo = b1_lo; b1_lo = d00; i1_lo = c0; }
            else if (d00 < b2_lo) { b2_lo = d00; }
            if (d01 < b1_lo) { b2_lo = b1_lo; b1_lo = d01; i1_lo = c0 + 1; }
            else if (d01 < b2_lo) { b2_lo = d01; }
            if (d10 < b1_hi) { b2_hi = b1_hi; b1_hi = d10; i1_hi = c0; }
            else if (d10 < b2_hi) { b2_hi = d10; }
            if (d11 < b1_hi) { b2_hi = b1_hi; b1_hi = d11; i1_hi = c0 + 1; }
            else if (d11 < b2_hi) { b2_hi = d11; }
        }
    }

    // ---- merge best1/best2 across the 4 lanes of each row group ----
    #pragma unroll
    for (int m = 1; m <= 2; m <<= 1) {
        float ob1 = __shfl_xor_sync(0xffffffffu, b1_lo, m);
        int   oi1 = __shfl_xor_sync(0xffffffffu, i1_lo, m);
        float ob2 = __shfl_xor_sync(0xffffffffu, b2_lo, m);
        bool take = (ob1 < b1_lo) || (ob1 == b1_lo && oi1 < i1_lo);
        float nb2 = take ? fminf(b1_lo, ob2) : fminf(b2_lo, ob1);
        if (take) { b1_lo = ob1; i1_lo = oi1; }
        b2_lo = nb2;

        ob1 = __shfl_xor_sync(0xffffffffu, b1_hi, m);
        oi1 = __shfl_xor_sync(0xffffffffu, i1_hi, m);
        ob2 = __shfl_xor_sync(0xffffffffu, b2_hi, m);
        take = (ob1 < b1_hi) || (ob1 == b1_hi && oi1 < i1_hi);
        nb2 = take ? fminf(b1_hi, ob2) : fminf(b2_hi, ob1);
        if (take) { b1_hi = ob1; i1_hi = oi1; }
        b2_hi = nb2;
    }

    if (q == 0) {
        int t0 = warp_tok + r;
        int t1 = warp_tok + r + 8;
        g_idx[t0] = i1_lo;
        g_idx[t1] = i1_hi;
        if (__fadd_rn(b2_lo, -b1_lo) <= MARGIN) {
            int p = atomicAdd(&g_nflag, 1);
            g_flag[p] = t0;
        }
        if (__fadd_rn(b2_hi, -b1_hi) <= MARGIN) {
            int p = atomicAdd(&g_nflag, 1);
            g_flag[p] = t1;
        }
    }
}

// ---------------------------------------------------------------------------
// Kernel 2: exact re-rank of flagged tokens (identical rounding tree to R2)
// ---------------------------------------------------------------------------
__global__ __launch_bounds__(256)
void exact_kernel(const float* __restrict__ x, const float* __restrict__ emb) {
    __shared__ float sx[DIM];
    __shared__ float sxn;
    __shared__ unsigned long long red[256];
    int nf = g_nflag;

    for (int f = blockIdx.x; f < nf; f += gridDim.x) {
        int token = g_flag[f];
        __syncthreads();
        if (threadIdx.x < DIM) sx[threadIdx.x] = x[(size_t)token * DIM + threadIdx.x];
        __syncthreads();
        if (threadIdx.x == 0) {
            float s = 0.0f;
            for (int d = 0; d < DIM; d++) s = __fmaf_rn(sx[d], sx[d], s);
            sxn = s;
        }
        __syncthreads();
        float xn = sxn;

        unsigned long long bkey = 0xFFFFFFFFFFFFFFFFull;
        #pragma unroll 1
        for (int cc = 0; cc < 4; cc++) {
            int code = threadIdx.x * 4 + cc;
            const float* er = emb + (size_t)code * DIM;
            float s[8] = {0, 0, 0, 0, 0, 0, 0, 0};
            #pragma unroll
            for (int j = 0; j < 8; j++) {
                #pragma unroll
                for (int m = 0; m < 8; m++)
                    s[m] = __fmaf_rn(sx[j * 8 + m], __ldg(er + j * 8 + m), s[m]);
            }
            float lo  = __fadd_rn(__fadd_rn(s[0], s[2]), __fadd_rn(s[4], s[6]));
            float hi  = __fadd_rn(__fadd_rn(s[1], s[3]), __fadd_rn(s[5], s[7]));
            float dot = __fadd_rn(lo, hi);
            float d2  = __fadd_rn(__fmaf_rn(-2.0f, dot, xn), g_enorm[code]);
            unsigned u = __float_as_uint(d2);
            u = (u & 0x80000000u) ? ~u : (u | 0x80000000u);
            unsigned long long key = ((unsigned long long)u << 32) | (unsigned)code;
            if (key < bkey) bkey = key;
        }
        red[threadIdx.x] = bkey;
        __syncthreads();
        for (int st = 128; st > 0; st >>= 1) {
            if (threadIdx.x < st && red[threadIdx.x + st] < red[threadIdx.x])
                red[threadIdx.x] = red[threadIdx.x + st];
            __syncthreads();
        }
        if (threadIdx.x == 0) g_idx[token] = (int)(red[0] & 0xFFFFFFFFull);
    }
}

// ---------------------------------------------------------------------------
// Kernel 3: per-token epilogue — quantized write, loss, counts, dw atomics
// ---------------------------------------------------------------------------
__global__ __launch_bounds__(256)
void epilogue_kernel(const float* __restrict__ x,
                     const float* __restrict__ emb,
                     float* __restrict__ out) {
    int token = blockIdx.x * 256 + threadIdx.x;
    int bi = g_idx[token];

    const float4* xrow = (const float4*)(x + ((size_t)token << 6));
    const float4* erow = (const float4*)(emb + ((size_t)bi << 6));
    float4* orow = (float4*)(out + OFF_Q + ((size_t)token << 6));
    float* dwrow = g_dw + ((size_t)bi << 6);

    float lsum = 0.0f;
    #pragma unroll 4
    for (int j = 0; j < 16; j++) {
        float4 xv = __ldg(xrow + j);
        float4 q  = __ldg(erow + j);
        float4 o;
        o.x = __fadd_rn(xv.x, __fadd_rn(q.x, -xv.x));
        o.y = __fadd_rn(xv.y, __fadd_rn(q.y, -xv.y));
        o.z = __fadd_rn(xv.z, __fadd_rn(q.z, -xv.z));
        o.w = __fadd_rn(xv.w, __fadd_rn(q.w, -xv.w));
        orow[j] = o;
        float d0 = __fadd_rn(xv.x, -q.x);
        float d1 = __fadd_rn(xv.y, -q.y);
        float d2 = __fadd_rn(xv.z, -q.z);
        float d3 = __fadd_rn(xv.w, -q.w);
        lsum = __fmaf_rn(d0, d0, lsum);
        lsum = __fmaf_rn(d1, d1, lsum);
        lsum = __fmaf_rn(d2, d2, lsum);
        lsum = __fmaf_rn(d3, d3, lsum);
        atomicAdd(dwrow + 4*j + 0, xv.x);
        atomicAdd(dwrow + 4*j + 1, xv.y);
        atomicAdd(dwrow + 4*j + 2, xv.z);
        atomicAdd(dwrow + 4*j + 3, xv.w);
    }
    atomicAdd(&g_counts[bi], 1.0f);

    double dl = (double)lsum;
    #pragma unroll
    for (int off = 16; off > 0; off >>= 1)
        dl += __shfl_down_sync(0xffffffffu, dl, off);
    if ((threadIdx.x & 31) == 0) atomicAdd(&g_loss, dl);
}

// ---------------------------------------------------------------------------
// Kernel 4: K-sized reductions + scalars + counts/usage
// ---------------------------------------------------------------------------
__global__ void finalize_kernel(const float* __restrict__ ema_count,
                                const float* __restrict__ usage,
                                float* __restrict__ out) {
    __shared__ float red_n[1024];
    __shared__ float red_s[1024];
    int k = threadIdx.x;

    float c   = g_counts[k];
    float raw = __fadd_rn(__fmul_rn(0.999f, ema_count[k]), __fmul_rn(0.001f, c));

    float p   = c * (1.0f / 65536.0f);
    float ent = __fmul_rn(p, logf(__fadd_rn(p, 1e-10f)));

    red_n[k] = raw;
    red_s[k] = ent;
    __syncthreads();
    for (int s = 512; s > 0; s >>= 1) {
        if (k < s) {
            red_n[k] = __fadd_rn(red_n[k], red_n[k + s]);
            red_s[k] = __fadd_rn(red_s[k], red_s[k + s]);
        }
        __syncthreads();
    }
    float n    = red_n[0];
    float ssum = red_s[0];

    float ncnt = __fmul_rn(__fdiv_rn(__fadd_rn(raw, 1e-5f),
                                     __fadd_rn(n, 0.01024f)), n);
    out[OFF_CNT + k] = ncnt;
    out[OFF_USE + k] = __fmul_rn(__fadd_rn(usage[k], (c > 0.0f) ? 1.0f : 0.0f), 0.5f);

    if (k == 0) {
        float ml = (float)(g_loss * (1.0 / 4194304.0));
        out[OFF_CB] = ml;
        out[OFF_CM] = 0.25f * ml;
        out[OFF_P]  = expf(-ssum);
    }
}

// ---------------------------------------------------------------------------
// Kernel 5: new_weight / new_embedding
// ---------------------------------------------------------------------------
__global__ void ema_kernel(const float* __restrict__ ema_weight,
                           float* __restrict__ out) {
    int idx = blockIdx.x * 1024 + threadIdx.x;
    float nw = __fadd_rn(__fmul_rn(0.999f, ema_weight[idx]),
                         __fmul_rn(0.001f, g_dw[idx]));
    out[OFF_W + idx] = nw;
    out[OFF_E + idx] = __fdiv_rn(nw, out[OFF_CNT + (idx >> 6)]);
}

// ---------------------------------------------------------------------------
extern "C" void kernel_launch(void* const* d_in, const int* in_sizes, int n_in,
                              void* d_out, int out_size) {
    const float* x          = (const float*)d_in[0];
    const float* emb        = (const float*)d_in[1];
    const float* ema_count  = (const float*)d_in[2];
    const float* ema_weight = (const float*)d_in[3];
    const float* usage      = (const float*)d_in[4];
    float* out = (float*)d_out;

    setup_kernel<<<256, 256>>>(emb);
    mma_assign_kernel<<<NTOK / 128, 256>>>(x);
    exact_kernel<<<256, 256>>>(x, emb);
    epilogue_kernel<<<NTOK / 256, 256>>>(x, emb, out);
    finalize_kernel<<<1, 1024>>>(ema_count, usage, out);
    ema_kernel<<<64, 1024>>>(ema_weight, out);
}

// round 5
// speedup vs baseline: 2.6881x; 1.3685x over previous
#include <cuda_runtime.h>
#include <cuda_bf16.h>
#include <math.h>
#include <float.h>

// Problem constants
#define NTOK   65536
#define DIM    64
#define KCODES 1024
#define MARGIN 5e-4f

// Output layout (float32 concatenation of the reference tuple)
#define OFF_Q    0
#define OFF_CM   4194304
#define OFF_CB   4194305
#define OFF_P    4194306
#define OFF_E    4194307
#define OFF_CNT  (OFF_E + KCODES*DIM)
#define OFF_W    (OFF_CNT + KCODES)
#define OFF_USE  (OFF_W + KCODES*DIM)

// Scratch (static device globals; no cudaMalloc allowed)
__device__ float          g_counts[KCODES];
__device__ float          g_dw[KCODES * DIM];
__device__ float          g_enorm[KCODES];
// Pre-permuted bf16 hi/lo B operand: [code][256B row]
//   row = 32 u32 hi (fragment-ordered pairs) + 32 u32 lo
__device__ unsigned short g_staged[KCODES * 128];
__device__ int            g_idx[NTOK];
__device__ int            g_flag[NTOK];
__device__ int            g_nflag;
__device__ double         g_loss;

// ---- helpers --------------------------------------------------------------
__device__ __forceinline__ unsigned cvt_bf16x2(float hi, float lo) {
    unsigned r;
    asm("cvt.rn.bf16x2.f32 %0, %1, %2;" : "=r"(r) : "f"(hi), "f"(lo));
    return r;
}
__device__ __forceinline__ unsigned smem_u32(const void* p) {
    unsigned r;
    asm("{ .reg .u64 t; cvta.to.shared.u64 t, %1; cvt.u32.u64 %0, t; }"
        : "=r"(r) : "l"(p));
    return r;
}

#define MMA_BF16(d0,d1,d2,d3,a0,a1,a2,a3,b0,b1)                               \
    asm("mma.sync.aligned.m16n8k16.row.col.f32.bf16.bf16.f32 "                \
        "{%0,%1,%2,%3}, {%4,%5,%6,%7}, {%8,%9}, {%0,%1,%2,%3};"               \
        : "+f"(d0), "+f"(d1), "+f"(d2), "+f"(d3)                              \
        : "r"(a0), "r"(a1), "r"(a2), "r"(a3), "r"(b0), "r"(b1))

// ---------------------------------------------------------------------------
// Kernel 0: zero scratch; enorm; build pre-permuted bf16 hi/lo B operand.
// Permutation: for dim d, pair p=d>>1, ks=p>>3, pos=p&7:
//   word w = pos<4 ? 2*(ks*4+pos) : 2*(ks*4+pos-4)+1
// so LDS.64 at word 2*(ks*4+q) yields {b0,b1} of the m16n8k16 B fragment.
// ---------------------------------------------------------------------------
__global__ void setup_kernel(const float* __restrict__ emb) {
    int gtid = blockIdx.x * 256 + threadIdx.x;      // 0..65535
    g_dw[gtid] = 0.0f;
    if (gtid < KCODES) g_counts[gtid] = 0.0f;
    if (gtid == 0) { g_loss = 0.0; g_nflag = 0; }

    int c = gtid >> 6;      // code
    int d = gtid & 63;      // dim
    float e = __ldg(emb + gtid);
    __nv_bfloat16 hb = __float2bfloat16(e);
    float hf = __bfloat162float(hb);
    __nv_bfloat16 lb = __float2bfloat16(__fadd_rn(e, -hf));

    int p   = d >> 1;
    int ks  = p >> 3;
    int pos = p & 7;
    int w   = (pos < 4) ? 2 * (ks * 4 + pos) : 2 * (ks * 4 + pos - 4) + 1;
    int rb  = c * 128;                       // u16 row base
    g_staged[rb + w * 2 + (d & 1)]      = __bfloat16_as_ushort(hb);
    g_staged[rb + 64 + w * 2 + (d & 1)] = __bfloat16_as_ushort(lb);

    // enorm (identical reduction tree to the passing kernels)
    if (blockIdx.x < 64) {
        int code = blockIdx.x * 16 + (threadIdx.x >> 4);
        int sub  = threadIdx.x & 15;
        float4 v = __ldg(((const float4*)(emb + (size_t)code * DIM)) + sub);
        float s = __fmul_rn(v.x, v.x);
        s = __fmaf_rn(v.y, v.y, s);
        s = __fmaf_rn(v.z, v.z, s);
        s = __fmaf_rn(v.w, v.w, s);
        #pragma unroll
        for (int off = 8; off > 0; off >>= 1)
            s = __fadd_rn(s, __shfl_down_sync(0xffffffffu, s, off));
        if (sub == 0) g_enorm[code] = s;
    }
}

// ---------------------------------------------------------------------------
// Kernel 1: bf16 3-split MMA assign. CTA = 256 threads = 8 warps = 256 tokens
// (32 tokens/warp via 2 M-tiles). All 1024 codes per warp, 16 chunks of 64,
// double-buffered via cp.async.
// ---------------------------------------------------------------------------
#define ROWB 272              // smem row stride bytes (256 + 16 pad)

__global__ __launch_bounds__(256, 2)
void mma_assign_kernel(const float* __restrict__ x) {
    __shared__ __align__(16) unsigned char sbuf[2][64 * ROWB];
    __shared__ float sEN[KCODES];

    int tid  = threadIdx.x;
    int lane = tid & 31;
    int wid  = tid >> 5;
    int r    = lane >> 2;    // groupID
    int q    = lane & 3;     // thread-in-group
    int warptok = blockIdx.x * 256 + wid * 32;

    unsigned sb[2] = { smem_u32(sbuf[0]), smem_u32(sbuf[1]) };

    // prefetch chunk 0
    {
        const float4* src = (const float4*)g_staged;   // chunk 0 base
        #pragma unroll
        for (int k2 = 0; k2 < 4; k2++) {
            int i = tid + k2 * 256;
            asm volatile("cp.async.cg.shared.global [%0], [%1], 16;"
                :: "r"(sb[0] + (i >> 4) * ROWB + (i & 15) * 16), "l"(src + i)
                : "memory");
        }
        asm volatile("cp.async.commit_group;" ::: "memory");
    }

    // en table
    #pragma unroll
    for (int i = 0; i < 4; i++) sEN[i * 256 + tid] = g_enorm[i * 256 + tid];

    // ---- A fragments: 4 token rows x 4 ksteps x {pair q, pair q+4} hi/lo ----
    unsigned ahi[4][4][2], alo[4][4][2];
    #pragma unroll
    for (int t = 0; t < 4; t++) {
        const float* xr = x + (size_t)(warptok + t * 8 + r) * DIM + 2 * q;
        #pragma unroll
        for (int ks = 0; ks < 4; ks++) {
            float2 v0 = __ldg((const float2*)(xr + 16 * ks));
            float2 v1 = __ldg((const float2*)(xr + 16 * ks + 8));
            unsigned h0 = cvt_bf16x2(v0.y, v0.x);
            unsigned h1 = cvt_bf16x2(v1.y, v1.x);
            float h0l = __uint_as_float(h0 << 16);
            float h0h = __uint_as_float(h0 & 0xffff0000u);
            float h1l = __uint_as_float(h1 << 16);
            float h1h = __uint_as_float(h1 & 0xffff0000u);
            ahi[t][ks][0] = h0;
            ahi[t][ks][1] = h1;
            alo[t][ks][0] = cvt_bf16x2(__fadd_rn(v0.y, -h0h),
                                       __fadd_rn(v0.x, -h0l));
            alo[t][ks][1] = cvt_bf16x2(__fadd_rn(v1.y, -h1h),
                                       __fadd_rn(v1.x, -h1l));
        }
    }

    float b1[4] = {FLT_MAX, FLT_MAX, FLT_MAX, FLT_MAX};
    float b2[4] = {FLT_MAX, FLT_MAX, FLT_MAX, FLT_MAX};
    int   i1[4] = {0, 0, 0, 0};

    for (int c = 0; c < 16; c++) {
        if (c + 1 < 16) {
            const float4* src = ((const float4*)g_staged) + (c + 1) * 1024;
            unsigned dst = sb[(c + 1) & 1];
            #pragma unroll
            for (int k2 = 0; k2 < 4; k2++) {
                int i = tid + k2 * 256;
                asm volatile("cp.async.cg.shared.global [%0], [%1], 16;"
                    :: "r"(dst + (i >> 4) * ROWB + (i & 15) * 16), "l"(src + i)
                    : "memory");
            }
            asm volatile("cp.async.commit_group;" ::: "memory");
            asm volatile("cp.async.wait_group 1;" ::: "memory");
        } else {
            asm volatile("cp.async.wait_group 0;" ::: "memory");
        }
        __syncthreads();

        const unsigned char* buf = sbuf[c & 1];
        int cbase = c * 64;

        #pragma unroll 2
        for (int nt = 0; nt < 8; nt++) {
            const unsigned char* row = buf + (nt * 8 + r) * ROWB + q * 8;
            float d00 = 0, d01 = 0, d02 = 0, d03 = 0;   // tile0 accum
            float d10 = 0, d11 = 0, d12 = 0, d13 = 0;   // tile1 accum
            #pragma unroll
            for (int ks = 0; ks < 4; ks++) {
                unsigned long long bh =
                    *(const unsigned long long*)(row + ks * 32);
                unsigned long long bl =
                    *(const unsigned long long*)(row + 128 + ks * 32);
                unsigned bh0 = (unsigned)bh, bh1 = (unsigned)(bh >> 32);
                unsigned bl0 = (unsigned)bl, bl1 = (unsigned)(bl >> 32);
                // tile 0 (tokens warptok + r, + r+8)
                MMA_BF16(d00, d01, d02, d03,
                         ahi[0][ks][0], ahi[1][ks][0],
                         ahi[0][ks][1], ahi[1][ks][1], bh0, bh1);
                MMA_BF16(d00, d01, d02, d03,
                         ahi[0][ks][0], ahi[1][ks][0],
                         ahi[0][ks][1], ahi[1][ks][1], bl0, bl1);
                MMA_BF16(d00, d01, d02, d03,
                         alo[0][ks][0], alo[1][ks][0],
                         alo[0][ks][1], alo[1][ks][1], bh0, bh1);
                // tile 1 (tokens warptok + r+16, + r+24)
                MMA_BF16(d10, d11, d12, d13,
                         ahi[2][ks][0], ahi[3][ks][0],
                         ahi[2][ks][1], ahi[3][ks][1], bh0, bh1);
                MMA_BF16(d10, d11, d12, d13,
                         ahi[2][ks][0], ahi[3][ks][0],
                         ahi[2][ks][1], ahi[3][ks][1], bl0, bl1);
                MMA_BF16(d10, d11, d12, d13,
                         alo[2][ks][0], alo[3][ks][0],
                         alo[2][ks][1], alo[3][ks][1], bh0, bh1);
            }
            int c0 = cbase + nt * 8 + 2 * q;
            float en0 = sEN[c0], en1 = sEN[c0 + 1];
            float k00 = __fmaf_rn(-2.0f, d00, en0);   // token slot 0 (r)
            float k01 = __fmaf_rn(-2.0f, d01, en1);
            float k02 = __fmaf_rn(-2.0f, d02, en0);   // slot 1 (r+8)
            float k03 = __fmaf_rn(-2.0f, d03, en1);
            float k10 = __fmaf_rn(-2.0f, d10, en0);   // slot 2 (r+16)
            float k11 = __fmaf_rn(-2.0f, d11, en1);
            float k12 = __fmaf_rn(-2.0f, d12, en0);   // slot 3 (r+24)
            float k13 = __fmaf_rn(-2.0f, d13, en1);

            if (k00 < b1[0]) { b2[0] = b1[0]; b1[0] = k00; i1[0] = c0; }
            else if (k00 < b2[0]) b2[0] = k00;
            if (k01 < b1[0]) { b2[0] = b1[0]; b1[0] = k01; i1[0] = c0 + 1; }
            else if (k01 < b2[0]) b2[0] = k01;
            if (k02 < b1[1]) { b2[1] = b1[1]; b1[1] = k02; i1[1] = c0; }
            else if (k02 < b2[1]) b2[1] = k02;
            if (k03 < b1[1]) { b2[1] = b1[1]; b1[1] = k03; i1[1] = c0 + 1; }
            else if (k03 < b2[1]) b2[1] = k03;
            if (k10 < b1[2]) { b2[2] = b1[2]; b1[2] = k10; i1[2] = c0; }
            else if (k10 < b2[2]) b2[2] = k10;
            if (k11 < b1[2]) { b2[2] = b1[2]; b1[2] = k11; i1[2] = c0 + 1; }
            else if (k11 < b2[2]) b2[2] = k11;
            if (k12 < b1[3]) { b2[3] = b1[3]; b1[3] = k12; i1[3] = c0; }
            else if (k12 < b2[3]) b2[3] = k12;
            if (k13 < b1[3]) { b2[3] = b1[3]; b1[3] = k13; i1[3] = c0 + 1; }
            else if (k13 < b2[3]) b2[3] = k13;
        }
        __syncthreads();
    }

    // ---- merge best1/best2 across the 4 q-lanes of each row group ----
    #pragma unroll
    for (int s = 0; s < 4; s++) {
        #pragma unroll
        for (int m = 1; m <= 2; m <<= 1) {
            float ob1 = __shfl_xor_sync(0xffffffffu, b1[s], m);
            int   oi1 = __shfl_xor_sync(0xffffffffu, i1[s], m);
            float ob2 = __shfl_xor_sync(0xffffffffu, b2[s], m);
            bool take = (ob1 < b1[s]) || (ob1 == b1[s] && oi1 < i1[s]);
            float nb2 = take ? fminf(b1[s], ob2) : fminf(b2[s], ob1);
            if (take) { b1[s] = ob1; i1[s] = oi1; }
            b2[s] = nb2;
        }
    }

    if (q == 0) {
        #pragma unroll
        for (int s = 0; s < 4; s++) {
            int tok = warptok + s * 8 + r;
            g_idx[tok] = i1[s];
            if (__fadd_rn(b2[s], -b1[s]) <= MARGIN) {
                int p = atomicAdd(&g_nflag, 1);
                g_flag[p] = tok;
            }
        }
    }
}

// ---------------------------------------------------------------------------
// Kernel 2: exact re-rank of flagged tokens (identical rounding tree to R2)
// ---------------------------------------------------------------------------
__global__ __launch_bounds__(256)
void exact_kernel(const float* __restrict__ x, const float* __restrict__ emb) {
    __shared__ float sx[DIM];
    __shared__ float sxn;
    __shared__ unsigned long long red[256];
    int nf = g_nflag;

    for (int f = blockIdx.x; f < nf; f += gridDim.x) {
        int token = g_flag[f];
        __syncthreads();
        if (threadIdx.x < DIM) sx[threadIdx.x] = x[(size_t)token * DIM + threadIdx.x];
        __syncthreads();
        if (threadIdx.x == 0) {
            float s = 0.0f;
            for (int d = 0; d < DIM; d++) s = __fmaf_rn(sx[d], sx[d], s);
            sxn = s;
        }
        __syncthreads();
        float xn = sxn;

        unsigned long long bkey = 0xFFFFFFFFFFFFFFFFull;
        #pragma unroll 1
        for (int cc = 0; cc < 4; cc++) {
            int code = threadIdx.x * 4 + cc;
            const float* er = emb + (size_t)code * DIM;
            float s[8] = {0, 0, 0, 0, 0, 0, 0, 0};
            #pragma unroll
            for (int j = 0; j < 8; j++) {
                #pragma unroll
                for (int m = 0; m < 8; m++)
                    s[m] = __fmaf_rn(sx[j * 8 + m], __ldg(er + j * 8 + m), s[m]);
            }
            float lo  = __fadd_rn(__fadd_rn(s[0], s[2]), __fadd_rn(s[4], s[6]));
            float hi  = __fadd_rn(__fadd_rn(s[1], s[3]), __fadd_rn(s[5], s[7]));
            float dot = __fadd_rn(lo, hi);
            float d2  = __fadd_rn(__fmaf_rn(-2.0f, dot, xn), g_enorm[code]);
            unsigned u = __float_as_uint(d2);
            u = (u & 0x80000000u) ? ~u : (u | 0x80000000u);
            unsigned long long key = ((unsigned long long)u << 32) | (unsigned)code;
            if (key < bkey) bkey = key;
        }
        red[threadIdx.x] = bkey;
        __syncthreads();
        for (int st = 128; st > 0; st >>= 1) {
            if (threadIdx.x < st && red[threadIdx.x + st] < red[threadIdx.x])
                red[threadIdx.x] = red[threadIdx.x + st];
            __syncthreads();
        }
        if (threadIdx.x == 0) g_idx[token] = (int)(red[0] & 0xFFFFFFFFull);
    }
}

// ---------------------------------------------------------------------------
// Kernel 3: epilogue — 8 threads per token
// ---------------------------------------------------------------------------
__global__ __launch_bounds__(256)
void epilogue_kernel(const float* __restrict__ x,
                     const float* __restrict__ emb,
                     float* __restrict__ out) {
    int gid   = blockIdx.x * 256 + threadIdx.x;
    int token = gid >> 3;
    int part  = gid & 7;
    int bi = g_idx[token];

    const float4* xrow = (const float4*)(x + ((size_t)token << 6)) + part * 2;
    const float4* erow = (const float4*)(emb + ((size_t)bi << 6)) + part * 2;
    float4* orow = (float4*)(out + OFF_Q + ((size_t)token << 6)) + part * 2;
    float* dwrow = g_dw + ((size_t)bi << 6) + part * 8;

    float lsum = 0.0f;
    #pragma unroll
    for (int j = 0; j < 2; j++) {
        float4 xv = __ldg(xrow + j);
        float4 q  = __ldg(erow + j);
        float4 o;
        o.x = __fadd_rn(xv.x, __fadd_rn(q.x, -xv.x));
        o.y = __fadd_rn(xv.y, __fadd_rn(q.y, -xv.y));
        o.z = __fadd_rn(xv.z, __fadd_rn(q.z, -xv.z));
        o.w = __fadd_rn(xv.w, __fadd_rn(q.w, -xv.w));
        orow[j] = o;
        float d0 = __fadd_rn(xv.x, -q.x);
        float d1 = __fadd_rn(xv.y, -q.y);
        float d2 = __fadd_rn(xv.z, -q.z);
        float d3 = __fadd_rn(xv.w, -q.w);
        lsum = __fmaf_rn(d0, d0, lsum);
        lsum = __fmaf_rn(d1, d1, lsum);
        lsum = __fmaf_rn(d2, d2, lsum);
        lsum = __fmaf_rn(d3, d3, lsum);
        atomicAdd(dwrow + 4*j + 0, xv.x);
        atomicAdd(dwrow + 4*j + 1, xv.y);
        atomicAdd(dwrow + 4*j + 2, xv.z);
        atomicAdd(dwrow + 4*j + 3, xv.w);
    }
    if (part == 0) atomicAdd(&g_counts[bi], 1.0f);

    double dl = (double)lsum;
    #pragma unroll
    for (int off = 16; off > 0; off >>= 1)
        dl += __shfl_down_sync(0xffffffffu, dl, off);
    if ((threadIdx.x & 31) == 0) atomicAdd(&g_loss, dl);
}

// ---------------------------------------------------------------------------
// Kernel 4: K-sized reductions + scalars + counts/usage
// ---------------------------------------------------------------------------
__global__ void finalize_kernel(const float* __restrict__ ema_count,
                                const float* __restrict__ usage,
                                float* __restrict__ out) {
    __shared__ float red_n[1024];
    __shared__ float red_s[1024];
    int k = threadIdx.x;

    float c   = g_counts[k];
    float raw = __fadd_rn(__fmul_rn(0.999f, ema_count[k]), __fmul_rn(0.001f, c));

    float p   = c * (1.0f / 65536.0f);
    float ent = __fmul_rn(p, logf(__fadd_rn(p, 1e-10f)));

    red_n[k] = raw;
    red_s[k] = ent;
    __syncthreads();
    for (int s = 512; s > 0; s >>= 1) {
        if (k < s) {
            red_n[k] = __fadd_rn(red_n[k], red_n[k + s]);
            red_s[k] = __fadd_rn(red_s[k], red_s[k + s]);
        }
        __syncthreads();
    }
    float n    = red_n[0];
    float ssum = red_s[0];

    float ncnt = __fmul_rn(__fdiv_rn(__fadd_rn(raw, 1e-5f),
                                     __fadd_rn(n, 0.01024f)), n);
    out[OFF_CNT + k] = ncnt;
    out[OFF_USE + k] = __fmul_rn(__fadd_rn(usage[k], (c > 0.0f) ? 1.0f : 0.0f), 0.5f);

    if (k == 0) {
        float ml = (float)(g_loss * (1.0 / 4194304.0));
        out[OFF_CB] = ml;
        out[OFF_CM] = 0.25f * ml;
        out[OFF_P]  = expf(-ssum);
    }
}

// ---------------------------------------------------------------------------
// Kernel 5: new_weight / new_embedding
// ---------------------------------------------------------------------------
__global__ void ema_kernel(const float* __restrict__ ema_weight,
                           float* __restrict__ out) {
    int idx = blockIdx.x * 1024 + threadIdx.x;
    float nw = __fadd_rn(__fmul_rn(0.999f, ema_weight[idx]),
                         __fmul_rn(0.001f, g_dw[idx]));
    out[OFF_W + idx] = nw;
    out[OFF_E + idx] = __fdiv_rn(nw, out[OFF_CNT + (idx >> 6)]);
}

// ---------------------------------------------------------------------------
extern "C" void kernel_launch(void* const* d_in, const int* in_sizes, int n_in,
                              void* d_out, int out_size) {
    const float* x          = (const float*)d_in[0];
    const float* emb        = (const float*)d_in[1];
    const float* ema_count  = (const float*)d_in[2];
    const float* ema_weight = (const float*)d_in[3];
    const float* usage      = (const float*)d_in[4];
    float* out = (float*)d_out;

    setup_kernel<<<256, 256>>>(emb);
    mma_assign_kernel<<<NTOK / 256, 256>>>(x);
    exact_kernel<<<256, 256>>>(x, emb);
    epilogue_kernel<<<NTOK * 8 / 256, 256>>>(x, emb, out);
    finalize_kernel<<<1, 1024>>>(ema_count, usage, out);
    ema_kernel<<<64, 1024>>>(ema_weight, out);
}